// round 8
// baseline (speedup 1.0000x reference)
#include <cuda_runtime.h>
#include <math.h>

// ---------------------------------------------------------------------------
// DCWTv2InferenceCache: segment-tree cover-set attention decode step.
// Graph fork/join with residency budgeting:
//   side stream  : memset d_out -> indep_kernel (local window + small nodes +
//                  big-node qd/scale prep), 256-thr blocks that fit in the
//                  per-SM slot left free by the stream.
//   main stream  : memset g_f -> partial_kernel (1040 blocks = ~7/SM, leaves
//                  >=256 thr/SM for the side branch) -> [join] -> big_kernel.
// ---------------------------------------------------------------------------

#define TOKDIM   1024            // 16 heads * 64 dims
#define HEADS    16
#define HDIM     64
#define MAXBIG   16
#define MAXNODES 40
#define GRID_P   1040            // 152 SMs * ~7 blocks; leaves slots for indep

__device__ float g_f[(size_t)MAXBIG * 64 * TOKDIM];
__device__ float g_qd[MAXBIG * HEADS * HDIM];
__device__ float g_scale[MAXBIG];

struct PartParams {
    int  nBig;
    int  a[MAXBIG];              // token offset of node
    int  C[MAXBIG];              // chunks (of 64 tokens) in node
    float inv[MAXBIG];           // 1/C
    long unitBase[MAXBIG + 1];   // prefix of C[n]*64 units
};

struct IndepParams {
    int   nSmall;
    int   sdepth[MAXNODES];
    int   sK[MAXNODES];
    int   soff[MAXNODES];        // token offset in V
    int   nBig;
    int   bdepth[MAXBIG];
    float inv_n;
};

// ---- partial: balanced chunk means -> red into g_f --------------------------
__global__ void __launch_bounds__(256) partial_kernel(
    const float* __restrict__ V, PartParams P, long U)
{
    const int tid = threadIdx.x;
    long u  = (long)blockIdx.x       * U / GRID_P;
    long u1 = ((long)blockIdx.x + 1) * U / GRID_P;

    while (u < u1) {
        int n = 0;
        while (u >= P.unitBase[n + 1]) n++;
        long rem = u - P.unitBase[n];
        int  k   = (int)(rem / P.C[n]);
        int  c   = (int)(rem % P.C[n]);
        long run = P.C[n] - c;
        if (run > u1 - u) run = u1 - u;

        const float4* p = (const float4*)(V + ((long)P.a[n] + (long)c * 64 + k) * TOKDIM) + tid;
        const long STR = 64L * TOKDIM / 4;

        float4 a0 = {0,0,0,0}, a1 = {0,0,0,0}, a2 = {0,0,0,0}, a3 = {0,0,0,0};
        long r = 0;
        for (; r + 8 <= run; r += 8) {
            float4 x0 = p[0];
            float4 x1 = p[STR];
            float4 x2 = p[2 * STR];
            float4 x3 = p[3 * STR];
            float4 x4 = p[4 * STR];
            float4 x5 = p[5 * STR];
            float4 x6 = p[6 * STR];
            float4 x7 = p[7 * STR];
            a0.x += x0.x; a0.y += x0.y; a0.z += x0.z; a0.w += x0.w;
            a1.x += x1.x; a1.y += x1.y; a1.z += x1.z; a1.w += x1.w;
            a2.x += x2.x; a2.y += x2.y; a2.z += x2.z; a2.w += x2.w;
            a3.x += x3.x; a3.y += x3.y; a3.z += x3.z; a3.w += x3.w;
            a0.x += x4.x; a0.y += x4.y; a0.z += x4.z; a0.w += x4.w;
            a1.x += x5.x; a1.y += x5.y; a1.z += x5.z; a1.w += x5.w;
            a2.x += x6.x; a2.y += x6.y; a2.z += x6.z; a2.w += x6.w;
            a3.x += x7.x; a3.y += x7.y; a3.z += x7.z; a3.w += x7.w;
            p += 8 * STR;
        }
        for (; r < run; r++) {
            float4 x0 = p[0];
            a0.x += x0.x; a0.y += x0.y; a0.z += x0.z; a0.w += x0.w;
            p += STR;
        }
        float s = P.inv[n];
        float* o = g_f + ((long)n * 64 + k) * TOKDIM + tid * 4;
        atomicAdd(o + 0, ((a0.x + a1.x) + (a2.x + a3.x)) * s);
        atomicAdd(o + 1, ((a0.y + a1.y) + (a2.y + a3.y)) * s);
        atomicAdd(o + 2, ((a0.z + a1.z) + (a2.z + a3.z)) * s);
        atomicAdd(o + 3, ((a0.w + a1.w) + (a2.w + a3.w)) * s);
        u += run;
    }
}

// ---- indep: local window + small nodes + big-node qd/scale prep ------------
// grid.x = 16 (local) + nSmall*16 + nBig ; block = 256 (fits leftover slots).
__global__ void __launch_bounds__(256) indep_kernel(
    const float* __restrict__ V,
    const float* __restrict__ q,
    const float* __restrict__ W,
    const float* __restrict__ temp,
    IndepParams P, int pos, float* __restrict__ out)
{
    const int b    = blockIdx.x;
    const int tid  = threadIdx.x;
    const int lane = tid & 31;
    const int wrp  = tid >> 5;

    __shared__ float fW[64 * 65];
    __shared__ float s_sh[512];
    __shared__ float red[256];
    __shared__ float q_sh[HEADS * HDIM];
    __shared__ float qd[HDIM];
    __shared__ float s_scale, s_mx, s_sum;

    if (b < HEADS) {
        // ================= local-window attention =================
        const int h    = b;
        const int nloc = pos < 512 ? pos : 512;
        const int base = pos - nloc;

        if (tid < HDIM) q_sh[tid] = q[h * HDIM + tid];
        __syncthreads();

        // warp-cooperative scores: warp w handles tokens [w*64, w*64+64)
        // lane reads float2 of the token row (coalesced, 2 wavefronts/token)
        const float2 q2 = ((const float2*)q_sh)[lane];
        for (int t = wrp * 64; t < wrp * 64 + 64; t++) {
            float sc = -1e30f;
            if (t < nloc) {
                const float2 v2 = *(const float2*)(V + (long)(base + t) * TOKDIM + h * HDIM + lane * 2);
                float p = q2.x * v2.x + q2.y * v2.y;
                #pragma unroll
                for (int o = 16; o > 0; o >>= 1)
                    p += __shfl_xor_sync(0xffffffff, p, o);
                sc = p * 0.125f;
            }
            if (lane == 0) s_sh[t] = sc;
        }
        __syncthreads();

        // block max over 512
        red[tid] = fmaxf(s_sh[tid], s_sh[tid + 256]);
        __syncthreads();
        #pragma unroll
        for (int st = 128; st >= 32; st >>= 1) {
            if (tid < st) red[tid] = fmaxf(red[tid], red[tid + st]);
            __syncthreads();
        }
        if (tid < 32) {
            float m = red[tid];
            #pragma unroll
            for (int o = 16; o > 0; o >>= 1)
                m = fmaxf(m, __shfl_xor_sync(0xffffffff, m, o));
            if (tid == 0) s_mx = m;
        }
        __syncthreads();

        // exp + sum
        float lsum = 0.f;
        #pragma unroll
        for (int t = tid; t < 512; t += 256) {
            float e = (t < nloc) ? expf(s_sh[t] - s_mx) : 0.f;
            s_sh[t] = e;
            lsum += e;
        }
        red[tid] = lsum;
        __syncthreads();
        #pragma unroll
        for (int st = 128; st >= 32; st >>= 1) {
            if (tid < st) red[tid] += red[tid + st];
            __syncthreads();
        }
        if (tid < 32) {
            float sm = red[tid];
            #pragma unroll
            for (int o = 16; o > 0; o >>= 1)
                sm += __shfl_xor_sync(0xffffffff, sm, o);
            if (tid == 0) s_sum = sm;
        }
        __syncthreads();

        // weighted sum: 4 k-groups x 64 dims (coalesced, unrolled for MLP)
        {
            int g = tid >> 6, d = tid & 63;
            float acc = 0.f;
            #pragma unroll 8
            for (int k = g; k < nloc; k += 4)
                acc += s_sh[k] * V[(long)(base + k) * TOKDIM + h * HDIM + d];
            red[tid] = acc;
        }
        __syncthreads();
        if (tid < HDIM) {
            float o = (red[tid] + red[64 + tid]) + (red[128 + tid] + red[192 + tid]);
            atomicAdd(out + h * HDIM + tid, (s_sum > 0.f) ? (o / s_sum) : 0.f);
        }
    } else if (b < HEADS + P.nSmall * HEADS) {
        // ================= small cover-set node attention =================
        const int si    = (b - HEADS) >> 4;
        const int h     = (b - HEADS) & 15;
        const int depth = P.sdepth[si];
        const int K     = P.sK[si];

        if (tid < HDIM) q_sh[tid] = q[h * HDIM + tid];

        const float* Wd = W + (long)depth * HDIM * HDIM;
        #pragma unroll
        for (int i = tid; i < HDIM * HDIM; i += 256) {
            int d = i >> 6, e = i & 63;
            fW[e * 65 + d] = Wd[i];            // transposed, coalesced
        }
        if (tid == 0) {
            float t  = temp[depth];
            float sp = log1pf(expf(t));
            s_scale  = 1.0f / ((sp + 1e-6f) * 8.0f);
        }
        __syncthreads();

        if (tid < HDIM) {
            float acc = q_sh[tid];
            #pragma unroll
            for (int e = 0; e < HDIM; e++) acc += q_sh[e] * fW[e * 65 + tid];
            qd[tid] = acc;
        }
        __syncthreads();

        const float* fsrc = V + (long)P.soff[si] * TOKDIM;
        for (int i = tid; i < K * HDIM; i += 256) {
            int k = i >> 6, d = i & 63;
            fW[k * 65 + d] = fsrc[(long)k * TOKDIM + h * HDIM + d];
        }
        __syncthreads();

        float sc = -1e30f;
        if (tid < K) {
            float acc = 0.f;
            #pragma unroll
            for (int d = 0; d < HDIM; d++) acc += qd[d] * fW[tid * 65 + d];
            sc = acc * s_scale;
        }
        if (tid < 64) red[tid] = sc;
        __syncthreads();
        if (tid < 32) {
            float m = fmaxf(red[tid], red[tid + 32]);
            #pragma unroll
            for (int o = 16; o > 0; o >>= 1)
                m = fmaxf(m, __shfl_xor_sync(0xffffffff, m, o));
            if (tid == 0) s_mx = m;
        }
        __syncthreads();

        float e = (tid < K) ? expf(sc - s_mx) : 0.f;
        if (tid < 64) { s_sh[tid] = e; red[tid] = e; }
        __syncthreads();
        if (tid < 32) {
            float sm = red[tid] + red[tid + 32];
            #pragma unroll
            for (int o = 16; o > 0; o >>= 1)
                sm += __shfl_xor_sync(0xffffffff, sm, o);
            if (tid == 0) s_sum = sm;
        }
        __syncthreads();

        {
            int g = tid >> 6, d = tid & 63;
            float acc = 0.f;
            for (int k = g; k < K; k += 4) acc += s_sh[k] * fW[k * 65 + d];
            red[tid] = acc;
        }
        __syncthreads();
        if (tid < HDIM) {
            float o = (red[tid] + red[64 + tid]) + (red[128 + tid] + red[192 + tid]);
            atomicAdd(out + h * HDIM + tid, (o / s_sum) * P.inv_n);
        }
    } else {
        // ================= big-node qd/scale precompute =================
        const int bi    = b - HEADS - P.nSmall * HEADS;
        const int depth = P.bdepth[bi];

        for (int i = tid; i < HEADS * HDIM; i += 256) q_sh[i] = q[i];

        const float* Wd = W + (long)depth * HDIM * HDIM;
        #pragma unroll
        for (int i = tid; i < HDIM * HDIM; i += 256) {
            int d = i >> 6, e = i & 63;
            fW[e * 65 + d] = Wd[i];
        }
        if (tid == 0) {
            float t  = temp[depth];
            float sp = log1pf(expf(t));
            g_scale[bi] = 1.0f / ((sp + 1e-6f) * 8.0f);
        }
        __syncthreads();

        // qd[h][d] = q[h][d] + sum_e q[h][e] * W[d][e]
        #pragma unroll
        for (int idx = tid; idx < HEADS * HDIM; idx += 256) {
            int h = idx >> 6, d = idx & 63;
            float acc = q_sh[h * HDIM + d];
            #pragma unroll
            for (int e = 0; e < HDIM; e++)
                acc += q_sh[h * HDIM + e] * fW[e * 65 + d];
            g_qd[bi * HEADS * HDIM + idx] = acc;
        }
    }
}

// ---- big-node attention: pure L2 (g_f + g_qd), K=64 always -----------------
__global__ void __launch_bounds__(256) big_kernel(
    IndepParams P, float* __restrict__ out)
{
    const int bi  = blockIdx.x >> 4;
    const int h   = blockIdx.x & 15;
    const int tid = threadIdx.x;

    __shared__ float f_sh[64 * 65];
    __shared__ float qd_sh[HDIM];
    __shared__ float s_sh[64];
    __shared__ float red[256];
    __shared__ float s_mx, s_sum;

    if (tid < HDIM) qd_sh[tid] = g_qd[bi * HEADS * HDIM + h * HDIM + tid];

    const float* fsrc = g_f + (long)bi * 64 * TOKDIM;
    for (int i = tid; i < 64 * HDIM; i += 256) {
        int k = i >> 6, d = i & 63;
        f_sh[k * 65 + d] = fsrc[(long)k * TOKDIM + h * HDIM + d];
    }
    __syncthreads();

    float sc = -1e30f;
    if (tid < 64) {
        float acc = 0.f;
        #pragma unroll
        for (int d = 0; d < HDIM; d++) acc += qd_sh[d] * f_sh[tid * 65 + d];
        sc = acc * g_scale[bi];
    }
    if (tid < 64) red[tid] = sc;
    __syncthreads();
    if (tid < 32) {
        float m = fmaxf(red[tid], red[tid + 32]);
        #pragma unroll
        for (int o = 16; o > 0; o >>= 1)
            m = fmaxf(m, __shfl_xor_sync(0xffffffff, m, o));
        if (tid == 0) s_mx = m;
    }
    __syncthreads();

    float e = (tid < 64) ? expf(sc - s_mx) : 0.f;
    if (tid < 64) { s_sh[tid] = e; red[tid] = e; }
    __syncthreads();
    if (tid < 32) {
        float sm = red[tid] + red[tid + 32];
        #pragma unroll
        for (int o = 16; o > 0; o >>= 1)
            sm += __shfl_xor_sync(0xffffffff, sm, o);
        if (tid == 0) s_sum = sm;
    }
    __syncthreads();

    {
        int g = tid >> 6, d = tid & 63;
        float acc = 0.f;
        for (int k = g; k < 64; k += 4) acc += s_sh[k] * f_sh[k * 65 + d];
        red[tid] = acc;
    }
    __syncthreads();
    if (tid < HDIM) {
        float o = (red[tid] + red[64 + tid]) + (red[128 + tid] + red[192 + tid]);
        atomicAdd(out + h * HDIM + tid, (o / s_sum) * P.inv_n);
    }
}

// ---------------------------------------------------------------------------
extern "C" void kernel_launch(void* const* d_in, const int* in_sizes, int n_in,
                              void* d_out, int out_size)
{
    const float* V    = (const float*)d_in[0];
    const float* q    = (const float*)d_in[1];
    const float* W    = (const float*)d_in[2];
    const float* temp = (const float*)d_in[3];

    const int pos = in_sizes[0] / TOKDIM;

    const int  LOG_N      = 17;
    const long LEAF_START = 1L << LOG_N;
    const long MAX_LEN    = 65536;

    PartParams  bp; bp.nBig = 0;
    IndepParams ip; ip.nSmall = 0; ip.nBig = 0;
    int nTotal = 0;

    auto addNode = [&](long idx) {
        int fl = 0; long t = idx;
        while (t > 1) { t >>= 1; fl++; }
        int depth = LOG_N - fl;
        long L = 1L << depth;
        long a = (idx << depth) - LEAF_START;
        nTotal++;
        if (L > 64) {
            int bi = bp.nBig++;
            bp.a[bi]   = (int)a;
            bp.C[bi]   = (int)(L / 64);
            bp.inv[bi] = 1.0f / (float)(L / 64);
            ip.bdepth[ip.nBig++] = depth;
        } else {
            int si = ip.nSmall++;
            ip.sdepth[si] = depth;
            ip.sK[si]     = (int)L;
            ip.soff[si]   = (int)a;
        }
    };

    long l = LEAF_START;
    long r = LEAF_START + (pos < MAX_LEN ? (long)pos : MAX_LEN);
    while (l < r) {
        if (l & 1) { addNode(l); l++; }
        if (r & 1) { r--; addNode(r); }
        l >>= 1; r >>= 1;
    }
    ip.inv_n = nTotal > 0 ? 1.0f / (float)nTotal : 0.f;

    bp.unitBase[0] = 0;
    for (int i = 0; i < bp.nBig; i++)
        bp.unitBase[i + 1] = bp.unitBase[i] + (long)bp.C[i] * 64;
    long U = bp.nBig ? bp.unitBase[bp.nBig] : 0;

    // lazy-init side stream + events (created on the uncaptured correctness call)
    static cudaStream_t s1 = nullptr;
    static cudaEvent_t  e1 = nullptr, e2 = nullptr;
    if (!s1) {
        cudaStreamCreateWithFlags(&s1, cudaStreamNonBlocking);
        cudaEventCreateWithFlags(&e1, cudaEventDisableTiming);
        cudaEventCreateWithFlags(&e2, cudaEventDisableTiming);
    }

    // fork
    cudaEventRecord(e1, 0);
    cudaStreamWaitEvent(s1, e1, 0);

    // side branch first (scheduler places its small blocks promptly)
    cudaMemsetAsync(d_out, 0, (size_t)out_size * sizeof(float), s1);
    int gridA = HEADS + ip.nSmall * HEADS + ip.nBig;
    indep_kernel<<<gridA, 256, 0, s1>>>(V, q, W, temp, ip, pos, (float*)d_out);
    cudaEventRecord(e2, s1);

    // main branch: HBM stream (grid leaves >=256 thr/SM free for the side branch)
    if (bp.nBig > 0) {
        void* gf_ptr = nullptr;
        cudaGetSymbolAddress(&gf_ptr, g_f);
        cudaMemsetAsync(gf_ptr, 0, (size_t)bp.nBig * 64 * TOKDIM * sizeof(float));
        partial_kernel<<<GRID_P, 256>>>(V, bp, U);
    }

    // join, then big-node epilogue (needs g_f + g_qd)
    cudaStreamWaitEvent(0, e2, 0);
    if (bp.nBig > 0)
        big_kernel<<<bp.nBig * HEADS, 256>>>(ip, (float*)d_out);
}

// round 9
// speedup vs baseline: 1.2871x; 1.2871x over previous
#include <cuda_runtime.h>
#include <math.h>

// ---------------------------------------------------------------------------
// DCWTv2InferenceCache: segment-tree cover-set attention decode step.
// Graph fork/join:
//   side stream : memset d_out -> indep_kernel (local window + small nodes +
//                 big-node qd/scale prep), launched FIRST so its 52 blocks
//                 get placed before the stream floods the SMs.
//   main stream : memset g_f -> partial_kernel (1216 blocks, R3-proven
//                 5.5 TB/s config) -> [join] -> big_kernel (L2-only).
// ---------------------------------------------------------------------------

#define TOKDIM   1024            // 16 heads * 64 dims
#define HEADS    16
#define HDIM     64
#define MAXBIG   16
#define MAXNODES 40
#define GRID_P   1216            // R3-proven streaming grid

__device__ float g_f[(size_t)MAXBIG * 64 * TOKDIM];
__device__ float g_qd[MAXBIG * HEADS * HDIM];
__device__ float g_scale[MAXBIG];

struct PartParams {
    int  nBig;
    int  a[MAXBIG];              // token offset of node
    int  C[MAXBIG];              // chunks (of 64 tokens) in node
    float inv[MAXBIG];           // 1/C
    long unitBase[MAXBIG + 1];   // prefix of C[n]*64 units
};

struct IndepParams {
    int   nSmall;
    int   sdepth[MAXNODES];
    int   sK[MAXNODES];
    int   soff[MAXNODES];        // token offset in V
    int   nBig;
    int   bdepth[MAXBIG];
    float inv_n;
};

// ---- partial: balanced chunk means -> red into g_f (R3 config) --------------
__global__ void __launch_bounds__(256) partial_kernel(
    const float* __restrict__ V, PartParams P, long U)
{
    const int tid = threadIdx.x;
    long u  = (long)blockIdx.x       * U / GRID_P;
    long u1 = ((long)blockIdx.x + 1) * U / GRID_P;

    while (u < u1) {
        int n = 0;
        while (u >= P.unitBase[n + 1]) n++;
        long rem = u - P.unitBase[n];
        int  k   = (int)(rem / P.C[n]);
        int  c   = (int)(rem % P.C[n]);
        long run = P.C[n] - c;
        if (run > u1 - u) run = u1 - u;

        const float4* p = (const float4*)(V + ((long)P.a[n] + (long)c * 64 + k) * TOKDIM) + tid;
        const long STR = 64L * TOKDIM / 4;

        float4 a0 = {0,0,0,0}, a1 = {0,0,0,0}, a2 = {0,0,0,0}, a3 = {0,0,0,0};
        long r = 0;
        for (; r + 8 <= run; r += 8) {
            float4 x0 = p[0];
            float4 x1 = p[STR];
            float4 x2 = p[2 * STR];
            float4 x3 = p[3 * STR];
            float4 x4 = p[4 * STR];
            float4 x5 = p[5 * STR];
            float4 x6 = p[6 * STR];
            float4 x7 = p[7 * STR];
            a0.x += x0.x; a0.y += x0.y; a0.z += x0.z; a0.w += x0.w;
            a1.x += x1.x; a1.y += x1.y; a1.z += x1.z; a1.w += x1.w;
            a2.x += x2.x; a2.y += x2.y; a2.z += x2.z; a2.w += x2.w;
            a3.x += x3.x; a3.y += x3.y; a3.z += x3.z; a3.w += x3.w;
            a0.x += x4.x; a0.y += x4.y; a0.z += x4.z; a0.w += x4.w;
            a1.x += x5.x; a1.y += x5.y; a1.z += x5.z; a1.w += x5.w;
            a2.x += x6.x; a2.y += x6.y; a2.z += x6.z; a2.w += x6.w;
            a3.x += x7.x; a3.y += x7.y; a3.z += x7.z; a3.w += x7.w;
            p += 8 * STR;
        }
        for (; r < run; r++) {
            float4 x0 = p[0];
            a0.x += x0.x; a0.y += x0.y; a0.z += x0.z; a0.w += x0.w;
            p += STR;
        }
        float s = P.inv[n];
        float* o = g_f + ((long)n * 64 + k) * TOKDIM + tid * 4;
        atomicAdd(o + 0, ((a0.x + a1.x) + (a2.x + a3.x)) * s);
        atomicAdd(o + 1, ((a0.y + a1.y) + (a2.y + a3.y)) * s);
        atomicAdd(o + 2, ((a0.z + a1.z) + (a2.z + a3.z)) * s);
        atomicAdd(o + 3, ((a0.w + a1.w) + (a2.w + a3.w)) * s);
        u += run;
    }
}

// ---- indep: local window + small nodes + big-node qd/scale prep ------------
// grid.x = 16 (local) + nSmall*16 + nBig ; block = 256.
__global__ void __launch_bounds__(256) indep_kernel(
    const float* __restrict__ V,
    const float* __restrict__ q,
    const float* __restrict__ W,
    const float* __restrict__ temp,
    IndepParams P, int pos, float* __restrict__ out)
{
    const int b   = blockIdx.x;
    const int tid = threadIdx.x;

    __shared__ float fW[64 * 65];
    __shared__ float s_sh[512];
    __shared__ float red[256];
    __shared__ float q_sh[HEADS * HDIM];
    __shared__ float qd[HDIM];
    __shared__ float s_scale, s_mx, s_sum;

    if (b < HEADS) {
        // ================= local-window attention =================
        const int h    = b;
        const int nloc = pos < 512 ? pos : 512;
        const int base = pos - nloc;

        if (tid < HDIM) q_sh[tid] = q[h * HDIM + tid];
        s_sh[tid]       = -1e30f;
        s_sh[tid + 256] = -1e30f;
        __syncthreads();

        // per-thread scores, 2 tokens per thread, 16 float4 in flight each
        for (int t = tid; t < nloc; t += 256) {
            const float4* vp = (const float4*)(V + (long)(base + t) * TOKDIM + h * HDIM);
            const float4* qp = (const float4*)q_sh;
            float acc = 0.f;
            #pragma unroll
            for (int i = 0; i < 16; i++) {
                float4 x  = vp[i];
                float4 qq = qp[i];
                acc += x.x * qq.x + x.y * qq.y + x.z * qq.z + x.w * qq.w;
            }
            s_sh[t] = acc * 0.125f;            // 1/sqrt(64)
        }
        __syncthreads();

        // block max over 512
        red[tid] = fmaxf(s_sh[tid], s_sh[tid + 256]);
        __syncthreads();
        #pragma unroll
        for (int st = 128; st >= 32; st >>= 1) {
            if (tid < st) red[tid] = fmaxf(red[tid], red[tid + st]);
            __syncthreads();
        }
        if (tid < 32) {
            float m = red[tid];
            #pragma unroll
            for (int o = 16; o > 0; o >>= 1)
                m = fmaxf(m, __shfl_xor_sync(0xffffffff, m, o));
            if (tid == 0) s_mx = m;
        }
        __syncthreads();

        // exp + sum
        float lsum = 0.f;
        #pragma unroll
        for (int t = tid; t < 512; t += 256) {
            float e = (t < nloc) ? expf(s_sh[t] - s_mx) : 0.f;
            s_sh[t] = e;
            lsum += e;
        }
        red[tid] = lsum;
        __syncthreads();
        #pragma unroll
        for (int st = 128; st >= 32; st >>= 1) {
            if (tid < st) red[tid] += red[tid + st];
            __syncthreads();
        }
        if (tid < 32) {
            float sm = red[tid];
            #pragma unroll
            for (int o = 16; o > 0; o >>= 1)
                sm += __shfl_xor_sync(0xffffffff, sm, o);
            if (tid == 0) s_sum = sm;
        }
        __syncthreads();

        // weighted sum: 4 k-groups x 64 dims (coalesced, unrolled for MLP)
        {
            int g = tid >> 6, d = tid & 63;
            float acc = 0.f;
            #pragma unroll 8
            for (int k = g; k < nloc; k += 4)
                acc += s_sh[k] * V[(long)(base + k) * TOKDIM + h * HDIM + d];
            red[tid] = acc;
        }
        __syncthreads();
        if (tid < HDIM) {
            float o = (red[tid] + red[64 + tid]) + (red[128 + tid] + red[192 + tid]);
            atomicAdd(out + h * HDIM + tid, (s_sum > 0.f) ? (o / s_sum) : 0.f);
        }
    } else if (b < HEADS + P.nSmall * HEADS) {
        // ================= small cover-set node attention =================
        const int si    = (b - HEADS) >> 4;
        const int h     = (b - HEADS) & 15;
        const int depth = P.sdepth[si];
        const int K     = P.sK[si];

        if (tid < HDIM) q_sh[tid] = q[h * HDIM + tid];

        const float* Wd = W + (long)depth * HDIM * HDIM;
        #pragma unroll
        for (int i = tid; i < HDIM * HDIM; i += 256) {
            int d = i >> 6, e = i & 63;
            fW[e * 65 + d] = Wd[i];            // transposed, coalesced
        }
        if (tid == 0) {
            float t  = temp[depth];
            float sp = log1pf(expf(t));
            s_scale  = 1.0f / ((sp + 1e-6f) * 8.0f);
        }
        __syncthreads();

        if (tid < HDIM) {
            float acc = q_sh[tid];
            #pragma unroll
            for (int e = 0; e < HDIM; e++) acc += q_sh[e] * fW[e * 65 + tid];
            qd[tid] = acc;
        }
        __syncthreads();

        const float* fsrc = V + (long)P.soff[si] * TOKDIM;
        for (int i = tid; i < K * HDIM; i += 256) {
            int k = i >> 6, d = i & 63;
            fW[k * 65 + d] = fsrc[(long)k * TOKDIM + h * HDIM + d];
        }
        __syncthreads();

        float sc = -1e30f;
        if (tid < K) {
            float acc = 0.f;
            #pragma unroll
            for (int d = 0; d < HDIM; d++) acc += qd[d] * fW[tid * 65 + d];
            sc = acc * s_scale;
        }
        if (tid < 64) red[tid] = sc;
        __syncthreads();
        if (tid < 32) {
            float m = fmaxf(red[tid], red[tid + 32]);
            #pragma unroll
            for (int o = 16; o > 0; o >>= 1)
                m = fmaxf(m, __shfl_xor_sync(0xffffffff, m, o));
            if (tid == 0) s_mx = m;
        }
        __syncthreads();

        float e = (tid < K) ? expf(sc - s_mx) : 0.f;
        if (tid < 64) { s_sh[tid] = e; red[tid] = e; }
        __syncthreads();
        if (tid < 32) {
            float sm = red[tid] + red[tid + 32];
            #pragma unroll
            for (int o = 16; o > 0; o >>= 1)
                sm += __shfl_xor_sync(0xffffffff, sm, o);
            if (tid == 0) s_sum = sm;
        }
        __syncthreads();

        {
            int g = tid >> 6, d = tid & 63;
            float acc = 0.f;
            for (int k = g; k < K; k += 4) acc += s_sh[k] * fW[k * 65 + d];
            red[tid] = acc;
        }
        __syncthreads();
        if (tid < HDIM) {
            float o = (red[tid] + red[64 + tid]) + (red[128 + tid] + red[192 + tid]);
            atomicAdd(out + h * HDIM + tid, (o / s_sum) * P.inv_n);
        }
    } else {
        // ================= big-node qd/scale precompute =================
        const int bi    = b - HEADS - P.nSmall * HEADS;
        const int depth = P.bdepth[bi];

        for (int i = tid; i < HEADS * HDIM; i += 256) q_sh[i] = q[i];

        const float* Wd = W + (long)depth * HDIM * HDIM;
        #pragma unroll
        for (int i = tid; i < HDIM * HDIM; i += 256) {
            int d = i >> 6, e = i & 63;
            fW[e * 65 + d] = Wd[i];
        }
        if (tid == 0) {
            float t  = temp[depth];
            float sp = log1pf(expf(t));
            g_scale[bi] = 1.0f / ((sp + 1e-6f) * 8.0f);
        }
        __syncthreads();

        // qd[h][d] = q[h][d] + sum_e q[h][e] * W[d][e]
        #pragma unroll
        for (int idx = tid; idx < HEADS * HDIM; idx += 256) {
            int h = idx >> 6, d = idx & 63;
            float acc = q_sh[h * HDIM + d];
            #pragma unroll
            for (int e = 0; e < HDIM; e++)
                acc += q_sh[h * HDIM + e] * fW[e * 65 + d];
            g_qd[bi * HEADS * HDIM + idx] = acc;
        }
    }
}

// ---- big-node attention: pure L2 (g_f + g_qd), K=64 always -----------------
__global__ void __launch_bounds__(256) big_kernel(
    IndepParams P, float* __restrict__ out)
{
    const int bi  = blockIdx.x >> 4;
    const int h   = blockIdx.x & 15;
    const int tid = threadIdx.x;

    __shared__ float f_sh[64 * 65];
    __shared__ float qd_sh[HDIM];
    __shared__ float s_sh[64];
    __shared__ float red[256];
    __shared__ float s_mx, s_sum;

    if (tid < HDIM) qd_sh[tid] = g_qd[bi * HEADS * HDIM + h * HDIM + tid];

    const float* fsrc = g_f + (long)bi * 64 * TOKDIM;
    for (int i = tid; i < 64 * HDIM; i += 256) {
        int k = i >> 6, d = i & 63;
        f_sh[k * 65 + d] = fsrc[(long)k * TOKDIM + h * HDIM + d];
    }
    __syncthreads();

    float sc = -1e30f;
    if (tid < 64) {
        float acc = 0.f;
        #pragma unroll
        for (int d = 0; d < HDIM; d++) acc += qd_sh[d] * f_sh[tid * 65 + d];
        sc = acc * g_scale[bi];
    }
    if (tid < 64) red[tid] = sc;
    __syncthreads();
    if (tid < 32) {
        float m = fmaxf(red[tid], red[tid + 32]);
        #pragma unroll
        for (int o = 16; o > 0; o >>= 1)
            m = fmaxf(m, __shfl_xor_sync(0xffffffff, m, o));
        if (tid == 0) s_mx = m;
    }
    __syncthreads();

    float e = (tid < 64) ? expf(sc - s_mx) : 0.f;
    if (tid < 64) { s_sh[tid] = e; red[tid] = e; }
    __syncthreads();
    if (tid < 32) {
        float sm = red[tid] + red[tid + 32];
        #pragma unroll
        for (int o = 16; o > 0; o >>= 1)
            sm += __shfl_xor_sync(0xffffffff, sm, o);
        if (tid == 0) s_sum = sm;
    }
    __syncthreads();

    {
        int g = tid >> 6, d = tid & 63;
        float acc = 0.f;
        for (int k = g; k < 64; k += 4) acc += s_sh[k] * f_sh[k * 65 + d];
        red[tid] = acc;
    }
    __syncthreads();
    if (tid < HDIM) {
        float o = (red[tid] + red[64 + tid]) + (red[128 + tid] + red[192 + tid]);
        atomicAdd(out + h * HDIM + tid, (o / s_sum) * P.inv_n);
    }
}

// ---------------------------------------------------------------------------
extern "C" void kernel_launch(void* const* d_in, const int* in_sizes, int n_in,
                              void* d_out, int out_size)
{
    const float* V    = (const float*)d_in[0];
    const float* q    = (const float*)d_in[1];
    const float* W    = (const float*)d_in[2];
    const float* temp = (const float*)d_in[3];

    const int pos = in_sizes[0] / TOKDIM;

    const int  LOG_N      = 17;
    const long LEAF_START = 1L << LOG_N;
    const long MAX_LEN    = 65536;

    PartParams  bp; bp.nBig = 0;
    IndepParams ip; ip.nSmall = 0; ip.nBig = 0;
    int nTotal = 0;

    auto addNode = [&](long idx) {
        int fl = 0; long t = idx;
        while (t > 1) { t >>= 1; fl++; }
        int depth = LOG_N - fl;
        long L = 1L << depth;
        long a = (idx << depth) - LEAF_START;
        nTotal++;
        if (L > 64) {
            int bi = bp.nBig++;
            bp.a[bi]   = (int)a;
            bp.C[bi]   = (int)(L / 64);
            bp.inv[bi] = 1.0f / (float)(L / 64);
            ip.bdepth[ip.nBig++] = depth;
        } else {
            int si = ip.nSmall++;
            ip.sdepth[si] = depth;
            ip.sK[si]     = (int)L;
            ip.soff[si]   = (int)a;
        }
    };

    long l = LEAF_START;
    long r = LEAF_START + (pos < MAX_LEN ? (long)pos : MAX_LEN);
    while (l < r) {
        if (l & 1) { addNode(l); l++; }
        if (r & 1) { r--; addNode(r); }
        l >>= 1; r >>= 1;
    }
    ip.inv_n = nTotal > 0 ? 1.0f / (float)nTotal : 0.f;

    bp.unitBase[0] = 0;
    for (int i = 0; i < bp.nBig; i++)
        bp.unitBase[i + 1] = bp.unitBase[i] + (long)bp.C[i] * 64;
    long U = bp.nBig ? bp.unitBase[bp.nBig] : 0;

    // lazy-init side stream + events (created on the uncaptured correctness call)
    static cudaStream_t s1 = nullptr;
    static cudaEvent_t  e1 = nullptr, e2 = nullptr;
    if (!s1) {
        cudaStreamCreateWithFlags(&s1, cudaStreamNonBlocking);
        cudaEventCreateWithFlags(&e1, cudaEventDisableTiming);
        cudaEventCreateWithFlags(&e2, cudaEventDisableTiming);
    }

    // fork
    cudaEventRecord(e1, 0);
    cudaStreamWaitEvent(s1, e1, 0);

    // side branch first (its 52 blocks get placed before the stream's flood)
    cudaMemsetAsync(d_out, 0, (size_t)out_size * sizeof(float), s1);
    int gridA = HEADS + ip.nSmall * HEADS + ip.nBig;
    indep_kernel<<<gridA, 256, 0, s1>>>(V, q, W, temp, ip, pos, (float*)d_out);
    cudaEventRecord(e2, s1);

    // main branch: HBM stream (R3-proven config)
    if (bp.nBig > 0) {
        void* gf_ptr = nullptr;
        cudaGetSymbolAddress(&gf_ptr, g_f);
        cudaMemsetAsync(gf_ptr, 0, (size_t)bp.nBig * 64 * TOKDIM * sizeof(float));
        partial_kernel<<<GRID_P, 256>>>(V, bp, U);
    }

    // join, then big-node epilogue (needs g_f + g_qd)
    cudaStreamWaitEvent(0, e2, 0);
    if (bp.nBig > 0)
        big_kernel<<<bp.nBig * HEADS, 256>>>(ip, (float*)d_out);
}